// round 3
// baseline (speedup 1.0000x reference)
#include <cuda_runtime.h>
#include <mma.h>
#include <cstdint>
#include <math.h>

using namespace nvcuda;

// ---------------- problem dims ----------------
#define Bn 64
#define Nn 256
#define Fn 16
#define Hn 256
#define ROWS (Bn*Nn)          // 16384
#define N_ITERS 10

// ---------------- scratch ----------------
__device__ float g_h  [ROWS*Hn];
__device__ float g_t  [ROWS*Hn];
__device__ float g_m  [ROWS*Hn];
__device__ float g_z  [ROWS*Hn];
__device__ float g_rh [ROWS*Hn];
__device__ float g_jcz[ROWS*Hn];
__device__ float g_jcr[ROWS*Hn];
__device__ float g_jch[ROWS*Hn];
__device__ float g_t2 [ROWS*Hn];

__device__ __forceinline__ float tf32_rnd(float x) {
    float r; asm("cvt.rna.tf32.f32 %0, %1;" : "=f"(r) : "f"(x)); return r;
}
__device__ __forceinline__ float sigf(float x) { return 1.0f / (1.0f + expf(-x)); }

// ---------------- wmma GEMM ----------------
// C[M,N] = epi(A[M,K] @ B[K,N] + extras). Block tile 128x128, 8 warps (2x4),
// warp tile 64x32 (4x2 frags of 16x16), K-chunk 32, 3xTF32 split.
enum { EPI_BIAS = 0, EPI_TANH, EPI_TANH_BIAS, EPI_SIG, EPI_SIGH, EPI_GRU };

// SMEM float offsets
#define LDA 40                  // 32 + 8 pad (160B row stride, 32B multiple)
#define LDB 136                 // 128 + 8 pad (544B row stride)
#define AHI_OFF 0               // 128*40 = 5120
#define ALO_OFF 5120
#define BHI_OFF 10240           // 32*136 = 4352
#define BLO_OFF 14592
#define SMEM_FLOATS 18944       // also holds C staging (16384) after reuse
#define SMEM_BYTES (SMEM_FLOATS*4)   // 75776

template<int EPI>
__global__ void __launch_bounds__(256)
tc_gemm(const float* A0, const float* A1,
        const float* B0, const float* B1,
        const float* __restrict__ bias, const float* __restrict__ jc,
        const float* __restrict__ Hb, const float* __restrict__ Zb,
        float* C, int K, int batched)
{
    extern __shared__ float sm[];
    float* Ahi = sm + AHI_OFF;
    float* Alo = sm + ALO_OFF;
    float* Bhi = sm + BHI_OFF;
    float* Blo = sm + BLO_OFF;

    const int tid = threadIdx.x, wid = tid >> 5;
    const int bn = blockIdx.x * 128, bm = blockIdx.y * 128;
    const int warp_m = wid >> 2;        // 0..1 -> 64 rows
    const int warp_n = wid & 3;         // 0..3 -> 32 cols

    const float* Ab = A0; const float* Bb = B0;
    int am = bm;
    if (batched) {
        const int b = bm >> 8;
        Ab = A0 + (size_t)b * (Nn * Hn);
        Bb = B0 + (size_t)b * (Nn * Hn);
        am = bm & (Nn - 1);
    }

    const int NC = K >> 5;

    auto srcs = [&](int kb, const float*& a, const float*& b) {
        const int kk = (kb & 7) * 32;
        if (kb < 8) { a = Ab + (size_t)am * Hn + kk; b = Bb + (size_t)kk * Hn + bn; }
        else        { a = A1 + (size_t)bm * Hn + kk; b = B1 + (size_t)(kk) * Hn + bn; }
    };

    // per-thread staging regs: 4 float4 for A (128x32), 4 float4 for B (32x128)
    float4 ra[4], rb[4];
    {
        const float *a, *b; srcs(0, a, b);
        #pragma unroll
        for (int i = 0; i < 4; i++) {
            int f = tid + i * 256;
            ra[i] = *(const float4*)(a + (size_t)(f >> 3) * Hn + (f & 7) * 4);
            rb[i] = *(const float4*)(b + (size_t)(f >> 5) * Hn + (f & 31) * 4);
        }
    }

    wmma::fragment<wmma::accumulator, 16, 16, 8, float> acc[4][2];
    #pragma unroll
    for (int mi = 0; mi < 4; mi++)
        #pragma unroll
        for (int ni = 0; ni < 2; ni++)
            wmma::fill_fragment(acc[mi][ni], 0.0f);

    for (int kb = 0; kb < NC; kb++) {
        __syncthreads();   // all warps done computing previous chunk
        // store staged chunk to smem with tf32 hi/lo split (rounded here;
        // fragments need no further conversion)
        #pragma unroll
        for (int i = 0; i < 4; i++) {
            const int f = tid + i * 256;
            {
                const int row = f >> 3, c4 = f & 7;
                float4 v = ra[i], hi, lo;
                hi.x = tf32_rnd(v.x); lo.x = tf32_rnd(v.x - hi.x);
                hi.y = tf32_rnd(v.y); lo.y = tf32_rnd(v.y - hi.y);
                hi.z = tf32_rnd(v.z); lo.z = tf32_rnd(v.z - hi.z);
                hi.w = tf32_rnd(v.w); lo.w = tf32_rnd(v.w - hi.w);
                *(float4*)(Ahi + row * LDA + c4 * 4) = hi;
                *(float4*)(Alo + row * LDA + c4 * 4) = lo;
            }
            {
                const int row = f >> 5, c4 = f & 31;
                float4 v = rb[i], hi, lo;
                hi.x = tf32_rnd(v.x); lo.x = tf32_rnd(v.x - hi.x);
                hi.y = tf32_rnd(v.y); lo.y = tf32_rnd(v.y - hi.y);
                hi.z = tf32_rnd(v.z); lo.z = tf32_rnd(v.z - hi.z);
                hi.w = tf32_rnd(v.w); lo.w = tf32_rnd(v.w - hi.w);
                *(float4*)(Bhi + row * LDB + c4 * 4) = hi;
                *(float4*)(Blo + row * LDB + c4 * 4) = lo;
            }
        }
        __syncthreads();

        // prefetch next chunk while computing this one
        if (kb + 1 < NC) {
            const float *a, *b; srcs(kb + 1, a, b);
            #pragma unroll
            for (int i = 0; i < 4; i++) {
                int f = tid + i * 256;
                ra[i] = *(const float4*)(a + (size_t)(f >> 3) * Hn + (f & 7) * 4);
                rb[i] = *(const float4*)(b + (size_t)(f >> 5) * Hn + (f & 31) * 4);
            }
        }

        #pragma unroll
        for (int kk = 0; kk < 4; kk++) {
            wmma::fragment<wmma::matrix_b, 16, 16, 8, wmma::precision::tf32, wmma::row_major> bh[2], bl[2];
            #pragma unroll
            for (int ni = 0; ni < 2; ni++) {
                const float* bp = Bhi + (kk * 8) * LDB + warp_n * 32 + ni * 16;
                const float* bq = Blo + (kk * 8) * LDB + warp_n * 32 + ni * 16;
                wmma::load_matrix_sync(bh[ni], bp, LDB);
                wmma::load_matrix_sync(bl[ni], bq, LDB);
            }
            #pragma unroll
            for (int mi = 0; mi < 4; mi++) {
                wmma::fragment<wmma::matrix_a, 16, 16, 8, wmma::precision::tf32, wmma::row_major> ah, al;
                const float* ap = Ahi + (warp_m * 64 + mi * 16) * LDA + kk * 8;
                const float* aq = Alo + (warp_m * 64 + mi * 16) * LDA + kk * 8;
                wmma::load_matrix_sync(ah, ap, LDA);
                wmma::load_matrix_sync(al, aq, LDA);
                #pragma unroll
                for (int ni = 0; ni < 2; ni++) {
                    wmma::mma_sync(acc[mi][ni], ah, bl[ni], acc[mi][ni]);
                    wmma::mma_sync(acc[mi][ni], al, bh[ni], acc[mi][ni]);
                    wmma::mma_sync(acc[mi][ni], ah, bh[ni], acc[mi][ni]);
                }
            }
        }
    }

    // ---------------- epilogue via smem staging ----------------
    __syncthreads();   // everyone done with operand smem
    float* Cs = sm;    // 128x128 floats
    #pragma unroll
    for (int mi = 0; mi < 4; mi++)
        #pragma unroll
        for (int ni = 0; ni < 2; ni++)
            wmma::store_matrix_sync(Cs + (warp_m * 64 + mi * 16) * 128 + warp_n * 32 + ni * 16,
                                    acc[mi][ni], 128, wmma::mem_row_major);
    __syncthreads();

    #pragma unroll
    for (int i = 0; i < 16; i++) {
        const int f = tid + i * 256;          // 4096 float4 slots
        const int row = f >> 5, c4 = f & 31;
        const int grow = bm + row, gcolb = bn + c4 * 4;
        const size_t base = (size_t)grow * Hn + gcolb;
        float4 v = *(float4*)(Cs + row * 128 + c4 * 4);

        if (EPI == EPI_BIAS || EPI == EPI_TANH_BIAS) {
            float4 bv = *(const float4*)(bias + gcolb);
            v.x += bv.x; v.y += bv.y; v.z += bv.z; v.w += bv.w;
            if (EPI == EPI_TANH_BIAS) { v.x=tanhf(v.x); v.y=tanhf(v.y); v.z=tanhf(v.z); v.w=tanhf(v.w); }
        } else if (EPI == EPI_TANH) {
            v.x=tanhf(v.x); v.y=tanhf(v.y); v.z=tanhf(v.z); v.w=tanhf(v.w);
        } else if (EPI == EPI_SIG) {
            float4 jv = *(const float4*)(jc + base);
            v.x=sigf(v.x+jv.x); v.y=sigf(v.y+jv.y); v.z=sigf(v.z+jv.z); v.w=sigf(v.w+jv.w);
        } else if (EPI == EPI_SIGH) {
            float4 jv = *(const float4*)(jc + base);
            float4 hv = *(const float4*)(Hb + base);
            v.x=sigf(v.x+jv.x)*hv.x; v.y=sigf(v.y+jv.y)*hv.y;
            v.z=sigf(v.z+jv.z)*hv.z; v.w=sigf(v.w+jv.w)*hv.w;
        } else if (EPI == EPI_GRU) {
            float4 jv = *(const float4*)(jc + base);
            float4 hv = *(const float4*)(Hb + base);
            float4 zv = *(const float4*)(Zb + base);
            float t0=tanhf(v.x+jv.x), t1=tanhf(v.y+jv.y), t2=tanhf(v.z+jv.z), t3=tanhf(v.w+jv.w);
            v.x = hv.x + zv.x*(t0-hv.x); v.y = hv.y + zv.y*(t1-hv.y);
            v.z = hv.z + zv.z*(t2-hv.z); v.w = hv.w + zv.w*(t3-hv.w);
        }
        *(float4*)(C + base) = v;
    }
}

// ---------------- small kernels ----------------
__global__ void emb_kernel(const float* __restrict__ jets, const float* __restrict__ W_emb,
                           const float* __restrict__ b_emb, float* __restrict__ h)
{
    const int row = blockIdx.x, j = threadIdx.x;
    __shared__ float sj[Fn];
    if (j < Fn) sj[j] = jets[(size_t)row * Fn + j];
    __syncthreads();
    float acc = b_emb[j];
    #pragma unroll
    for (int k = 0; k < Fn; k++) acc = fmaf(sj[k], W_emb[k * Hn + j], acc);
    h[(size_t)row * Hn + j] = tanhf(acc);
}

__global__ void jc_kernel(const float* __restrict__ jets,
                          const float* __restrict__ Wz, const float* __restrict__ Wr,
                          const float* __restrict__ Wh,
                          const float* __restrict__ bz, const float* __restrict__ br,
                          const float* __restrict__ bh,
                          float* jcz, float* jcr, float* jch)
{
    const int row = blockIdx.x, j = threadIdx.x;
    __shared__ float sj[Fn];
    if (j < Fn) sj[j] = jets[(size_t)row * Fn + j];
    __syncthreads();
    float az = bz[j], ar = br[j], ah = bh[j];
    #pragma unroll
    for (int k = 0; k < Fn; k++) {
        const float s = sj[k];
        const int widx = (Hn + k) * Hn + j;
        az = fmaf(s, Wz[widx], az);
        ar = fmaf(s, Wr[widx], ar);
        ah = fmaf(s, Wh[widx], ah);
    }
    const size_t idx = (size_t)row * Hn + j;
    jcz[idx] = az; jcr[idx] = ar; jch[idx] = ah;
}

__global__ void reduce_kernel(const float* __restrict__ t2, float* __restrict__ out)
{
    const int idx = blockIdx.x * blockDim.x + threadIdx.x;
    const int b = idx >> 8, j = idx & 255;
    const float* p = t2 + (size_t)b * (Nn * Hn) + j;
    float acc = 0.0f;
    for (int n = 0; n < Nn; n++) acc += p[(size_t)n * Hn];
    out[idx] = acc;
}

// ---------------- launch ----------------
extern "C" void kernel_launch(void* const* d_in, const int* in_sizes, int n_in,
                              void* d_out, int out_size)
{
    const float* jets  = (const float*)d_in[0];
    const float* dads  = (const float*)d_in[1];
    const float* W_emb = (const float*)d_in[2];
    const float* b_emb = (const float*)d_in[3];
    const float* W_msg = (const float*)d_in[4];
    const float* b_msg = (const float*)d_in[5];
    const float* Wz    = (const float*)d_in[6];
    const float* Uz    = (const float*)d_in[7];
    const float* bz    = (const float*)d_in[8];
    const float* Wr    = (const float*)d_in[9];
    const float* Ur    = (const float*)d_in[10];
    const float* br    = (const float*)d_in[11];
    const float* Wh    = (const float*)d_in[12];
    const float* Uh    = (const float*)d_in[13];
    const float* bh    = (const float*)d_in[14];
    const float* W_r1  = (const float*)d_in[15];
    const float* b_r1  = (const float*)d_in[16];
    const float* W_r2  = (const float*)d_in[17];
    const float* b_r2  = (const float*)d_in[18];
    float* out = (float*)d_out;

    float *h,*t,*m,*z,*rh,*jcz,*jcr,*jch,*t2;
    cudaGetSymbolAddress((void**)&h,   g_h);
    cudaGetSymbolAddress((void**)&t,   g_t);
    cudaGetSymbolAddress((void**)&m,   g_m);
    cudaGetSymbolAddress((void**)&z,   g_z);
    cudaGetSymbolAddress((void**)&rh,  g_rh);
    cudaGetSymbolAddress((void**)&jcz, g_jcz);
    cudaGetSymbolAddress((void**)&jcr, g_jcr);
    cudaGetSymbolAddress((void**)&jch, g_jch);
    cudaGetSymbolAddress((void**)&t2,  g_t2);

    static bool attr_done = false;
    if (!attr_done) {
        cudaFuncSetAttribute(tc_gemm<EPI_BIAS>,      cudaFuncAttributeMaxDynamicSharedMemorySize, SMEM_BYTES);
        cudaFuncSetAttribute(tc_gemm<EPI_TANH>,      cudaFuncAttributeMaxDynamicSharedMemorySize, SMEM_BYTES);
        cudaFuncSetAttribute(tc_gemm<EPI_TANH_BIAS>, cudaFuncAttributeMaxDynamicSharedMemorySize, SMEM_BYTES);
        cudaFuncSetAttribute(tc_gemm<EPI_SIG>,       cudaFuncAttributeMaxDynamicSharedMemorySize, SMEM_BYTES);
        cudaFuncSetAttribute(tc_gemm<EPI_SIGH>,      cudaFuncAttributeMaxDynamicSharedMemorySize, SMEM_BYTES);
        cudaFuncSetAttribute(tc_gemm<EPI_GRU>,       cudaFuncAttributeMaxDynamicSharedMemorySize, SMEM_BYTES);
        attr_done = true;
    }

    emb_kernel<<<ROWS, Hn>>>(jets, W_emb, b_emb, h);
    jc_kernel<<<ROWS, Hn>>>(jets, Wz, Wr, Wh, bz, br, bh, jcz, jcr, jch);

    dim3 grid(Hn/128, ROWS/128);   // (2, 128)
    for (int it = 0; it < N_ITERS; it++) {
        // t = h @ W_msg + b_msg
        tc_gemm<EPI_BIAS><<<grid, 256, SMEM_BYTES>>>(h, nullptr, W_msg, nullptr,
            b_msg, nullptr, nullptr, nullptr, t, 256, 0);
        // m = tanh(dads @ t)   (batched)
        tc_gemm<EPI_TANH><<<grid, 256, SMEM_BYTES>>>(dads, nullptr, t, nullptr,
            nullptr, nullptr, nullptr, nullptr, m, 256, 1);
        // z = sigmoid(m@Wz[:H] + h@Uz + jc_z)
        tc_gemm<EPI_SIG><<<grid, 256, SMEM_BYTES>>>(m, h, Wz, Uz,
            nullptr, jcz, nullptr, nullptr, z, 512, 0);
        // rh = sigmoid(m@Wr[:H] + h@Ur + jc_r) * h
        tc_gemm<EPI_SIGH><<<grid, 256, SMEM_BYTES>>>(m, h, Wr, Ur,
            nullptr, jcr, h, nullptr, rh, 512, 0);
        // h = (1-z)*h + z*tanh(m@Wh[:H] + rh@Uh + jc_h)
        tc_gemm<EPI_GRU><<<grid, 256, SMEM_BYTES>>>(m, rh, Wh, Uh,
            nullptr, jch, h, z, h, 512, 0);
    }

    tc_gemm<EPI_TANH_BIAS><<<grid, 256, SMEM_BYTES>>>(h, nullptr, W_r1, nullptr,
        b_r1, nullptr, nullptr, nullptr, t, 256, 0);
    tc_gemm<EPI_BIAS><<<grid, 256, SMEM_BYTES>>>(t, nullptr, W_r2, nullptr,
        b_r2, nullptr, nullptr, nullptr, t2, 256, 0);
    reduce_kernel<<<Bn, 256>>>(t2, out);
}

// round 4
// speedup vs baseline: 2.5048x; 2.5048x over previous
#include <cuda_runtime.h>
#include <mma.h>
#include <cuda_bf16.h>
#include <cstdint>
#include <math.h>

using namespace nvcuda;

// ---------------- problem dims ----------------
#define Bn 64
#define Nn 256
#define Fn 16
#define Hn 256
#define ROWS (Bn*Nn)          // 16384
#define N_ITERS 10

// ---------------- scratch ----------------
__device__ float g_h  [ROWS*Hn];
__device__ float g_t  [ROWS*Hn];
__device__ float g_m  [ROWS*Hn];
__device__ float g_z  [ROWS*Hn];
__device__ float g_rh [ROWS*Hn];
__device__ float g_jcz[ROWS*Hn];
__device__ float g_jcr[ROWS*Hn];
__device__ float g_jch[ROWS*Hn];
__device__ float g_t2 [ROWS*Hn];

__device__ __forceinline__ float sigf(float x) { return 1.0f / (1.0f + expf(-x)); }

// ---------------- bf16-split wmma GEMM ----------------
// C[M,N] = epi(A[M,K] @ B[K,N] + extras). Block tile 128x128, 8 warps (2x4),
// warp tile 64x32 (4x2 frags of 16x16), K-chunk 32, 2-way bf16 split x 3 passes.
enum { EPI_BIAS = 0, EPI_TANH, EPI_TANH_BIAS, EPI_SIG, EPI_SIGH, EPI_GRU };

// SMEM layout in bytes (bf16 elements)
#define LDA 40                  // 32 + 8 pad bf16 (80B rows)
#define LDB 136                 // 128 + 8 pad bf16 (272B rows)
#define A_BYTES (128*LDA*2)     // 10240 per (hi|lo)
#define B_BYTES (32*LDB*2)      // 8704 per (hi|lo)
#define AHI_OFF 0
#define ALO_OFF (A_BYTES)                 // 10240
#define BHI_OFF (2*A_BYTES)               // 20480
#define BLO_OFF (2*A_BYTES + B_BYTES)     // 29184
#define BUF_STRIDE (2*A_BYTES + 2*B_BYTES) // 37888
#define SMEM_BYTES (2*BUF_STRIDE)          // 75776 (also holds 64KB C staging)

// split a float4 into hi/lo bf16 quads packed as uint2 each
__device__ __forceinline__ void split4(float4 v, uint2& hi, uint2& lo) {
    __nv_bfloat162 h01 = __floats2bfloat162_rn(v.x, v.y);
    __nv_bfloat162 h23 = __floats2bfloat162_rn(v.z, v.w);
    float r0 = v.x - __low2float(h01), r1 = v.y - __high2float(h01);
    float r2 = v.z - __low2float(h23), r3 = v.w - __high2float(h23);
    __nv_bfloat162 l01 = __floats2bfloat162_rn(r0, r1);
    __nv_bfloat162 l23 = __floats2bfloat162_rn(r2, r3);
    hi.x = *(uint32_t*)&h01; hi.y = *(uint32_t*)&h23;
    lo.x = *(uint32_t*)&l01; lo.y = *(uint32_t*)&l23;
}

template<int EPI>
__global__ void __launch_bounds__(256)
tc_gemm(const float* A0, const float* A1,
        const float* B0, const float* B1,
        const float* __restrict__ bias, const float* __restrict__ jc,
        const float* __restrict__ Hb, const float* __restrict__ Zb,
        float* C, int K, int batched)
{
    extern __shared__ char sm[];

    const int tid = threadIdx.x, wid = tid >> 5;
    const int bn = blockIdx.x * 128, bm = blockIdx.y * 128;
    const int warp_m = wid >> 2;        // 0..1 -> 64 rows
    const int warp_n = wid & 3;         // 0..3 -> 32 cols

    const float* Ab = A0; const float* Bb = B0;
    int am = bm;
    if (batched) {
        const int b = bm >> 8;
        Ab = A0 + (size_t)b * (Nn * Hn);
        Bb = B0 + (size_t)b * (Nn * Hn);
        am = bm & (Nn - 1);
    }

    const int NC = K >> 5;

    auto srcs = [&](int kb, const float*& a, const float*& b) {
        const int kk = (kb & 7) * 32;
        if (kb < 8) { a = Ab + (size_t)am * Hn + kk; b = Bb + (size_t)kk * Hn + bn; }
        else        { a = A1 + (size_t)bm * Hn + kk; b = B1 + (size_t)kk * Hn + bn; }
    };

    // stage regs for one chunk: 4 float4 A + 4 float4 B per thread
    float4 ra[4], rb[4];
    auto stage = [&](int kb) {
        const float *a, *b; srcs(kb, a, b);
        #pragma unroll
        for (int i = 0; i < 4; i++) {
            const int f = tid + i * 256;
            ra[i] = *(const float4*)(a + (size_t)(f >> 3) * Hn + (f & 7) * 4);
            rb[i] = *(const float4*)(b + (size_t)(f >> 5) * Hn + (f & 31) * 4);
        }
    };
    auto commit = [&](int buf) {
        char* base = sm + buf * BUF_STRIDE;
        #pragma unroll
        for (int i = 0; i < 4; i++) {
            const int f = tid + i * 256;
            uint2 hi, lo;
            {
                const int row = f >> 3, c4 = f & 7;
                split4(ra[i], hi, lo);
                const uint32_t off = (uint32_t)(row * LDA + c4 * 4) * 2;
                *(uint2*)(base + AHI_OFF + off) = hi;
                *(uint2*)(base + ALO_OFF + off) = lo;
            }
            {
                const int row = f >> 5, c4 = f & 31;
                split4(rb[i], hi, lo);
                const uint32_t off = (uint32_t)(row * LDB + c4 * 4) * 2;
                *(uint2*)(base + BHI_OFF + off) = hi;
                *(uint2*)(base + BLO_OFF + off) = lo;
            }
        }
    };

    wmma::fragment<wmma::accumulator, 16, 16, 16, float> acc[4][2];
    #pragma unroll
    for (int mi = 0; mi < 4; mi++)
        #pragma unroll
        for (int ni = 0; ni < 2; ni++)
            wmma::fill_fragment(acc[mi][ni], 0.0f);

    stage(0);
    commit(0);
    __syncthreads();

    for (int kb = 0; kb < NC; kb++) {
        if (kb + 1 < NC) stage(kb + 1);   // gmem loads overlap compute below

        const char* base = sm + (kb & 1) * BUF_STRIDE;
        const __nv_bfloat16* Ahi = (const __nv_bfloat16*)(base + AHI_OFF);
        const __nv_bfloat16* Alo = (const __nv_bfloat16*)(base + ALO_OFF);
        const __nv_bfloat16* Bhi = (const __nv_bfloat16*)(base + BHI_OFF);
        const __nv_bfloat16* Blo = (const __nv_bfloat16*)(base + BLO_OFF);

        #pragma unroll
        for (int kk = 0; kk < 2; kk++) {
            wmma::fragment<wmma::matrix_b, 16, 16, 16, __nv_bfloat16, wmma::row_major> bh[2], bl[2];
            #pragma unroll
            for (int ni = 0; ni < 2; ni++) {
                wmma::load_matrix_sync(bh[ni], Bhi + (kk * 16) * LDB + warp_n * 32 + ni * 16, LDB);
                wmma::load_matrix_sync(bl[ni], Blo + (kk * 16) * LDB + warp_n * 32 + ni * 16, LDB);
            }
            #pragma unroll
            for (int mi = 0; mi < 4; mi++) {
                wmma::fragment<wmma::matrix_a, 16, 16, 16, __nv_bfloat16, wmma::row_major> ah, al;
                wmma::load_matrix_sync(ah, Ahi + (warp_m * 64 + mi * 16) * LDA + kk * 16, LDA);
                wmma::load_matrix_sync(al, Alo + (warp_m * 64 + mi * 16) * LDA + kk * 16, LDA);
                #pragma unroll
                for (int ni = 0; ni < 2; ni++) {
                    wmma::mma_sync(acc[mi][ni], ah, bl[ni], acc[mi][ni]);
                    wmma::mma_sync(acc[mi][ni], al, bh[ni], acc[mi][ni]);
                    wmma::mma_sync(acc[mi][ni], ah, bh[ni], acc[mi][ni]);
                }
            }
        }

        if (kb + 1 < NC) commit((kb + 1) & 1);   // write other buffer
        __syncthreads();
    }

    // ---------------- epilogue via smem staging ----------------
    float* Cs = (float*)sm;    // 128x128 floats (operand smem dead now)
    #pragma unroll
    for (int mi = 0; mi < 4; mi++)
        #pragma unroll
        for (int ni = 0; ni < 2; ni++)
            wmma::store_matrix_sync(Cs + (warp_m * 64 + mi * 16) * 128 + warp_n * 32 + ni * 16,
                                    acc[mi][ni], 128, wmma::mem_row_major);
    __syncthreads();

    #pragma unroll
    for (int i = 0; i < 16; i++) {
        const int f = tid + i * 256;
        const int row = f >> 5, c4 = f & 31;
        const int grow = bm + row, gcolb = bn + c4 * 4;
        const size_t base = (size_t)grow * Hn + gcolb;
        float4 v = *(float4*)(Cs + row * 128 + c4 * 4);

        if (EPI == EPI_BIAS || EPI == EPI_TANH_BIAS) {
            float4 bv = *(const float4*)(bias + gcolb);
            v.x += bv.x; v.y += bv.y; v.z += bv.z; v.w += bv.w;
            if (EPI == EPI_TANH_BIAS) { v.x=tanhf(v.x); v.y=tanhf(v.y); v.z=tanhf(v.z); v.w=tanhf(v.w); }
        } else if (EPI == EPI_TANH) {
            v.x=tanhf(v.x); v.y=tanhf(v.y); v.z=tanhf(v.z); v.w=tanhf(v.w);
        } else if (EPI == EPI_SIG) {
            float4 jv = *(const float4*)(jc + base);
            v.x=sigf(v.x+jv.x); v.y=sigf(v.y+jv.y); v.z=sigf(v.z+jv.z); v.w=sigf(v.w+jv.w);
        } else if (EPI == EPI_SIGH) {
            float4 jv = *(const float4*)(jc + base);
            float4 hv = *(const float4*)(Hb + base);
            v.x=sigf(v.x+jv.x)*hv.x; v.y=sigf(v.y+jv.y)*hv.y;
            v.z=sigf(v.z+jv.z)*hv.z; v.w=sigf(v.w+jv.w)*hv.w;
        } else if (EPI == EPI_GRU) {
            float4 jv = *(const float4*)(jc + base);
            float4 hv = *(const float4*)(Hb + base);
            float4 zv = *(const float4*)(Zb + base);
            float t0=tanhf(v.x+jv.x), t1=tanhf(v.y+jv.y), t2=tanhf(v.z+jv.z), t3=tanhf(v.w+jv.w);
            v.x = hv.x + zv.x*(t0-hv.x); v.y = hv.y + zv.y*(t1-hv.y);
            v.z = hv.z + zv.z*(t2-hv.z); v.w = hv.w + zv.w*(t3-hv.w);
        }
        *(float4*)(C + base) = v;
    }
}

// ---------------- small kernels ----------------
__global__ void emb_kernel(const float* __restrict__ jets, const float* __restrict__ W_emb,
                           const float* __restrict__ b_emb, float* __restrict__ h)
{
    const int row = blockIdx.x, j = threadIdx.x;
    __shared__ float sj[Fn];
    if (j < Fn) sj[j] = jets[(size_t)row * Fn + j];
    __syncthreads();
    float acc = b_emb[j];
    #pragma unroll
    for (int k = 0; k < Fn; k++) acc = fmaf(sj[k], W_emb[k * Hn + j], acc);
    h[(size_t)row * Hn + j] = tanhf(acc);
}

__global__ void jc_kernel(const float* __restrict__ jets,
                          const float* __restrict__ Wz, const float* __restrict__ Wr,
                          const float* __restrict__ Wh,
                          const float* __restrict__ bz, const float* __restrict__ br,
                          const float* __restrict__ bh,
                          float* jcz, float* jcr, float* jch)
{
    const int row = blockIdx.x, j = threadIdx.x;
    __shared__ float sj[Fn];
    if (j < Fn) sj[j] = jets[(size_t)row * Fn + j];
    __syncthreads();
    float az = bz[j], ar = br[j], ah = bh[j];
    #pragma unroll
    for (int k = 0; k < Fn; k++) {
        const float s = sj[k];
        const int widx = (Hn + k) * Hn + j;
        az = fmaf(s, Wz[widx], az);
        ar = fmaf(s, Wr[widx], ar);
        ah = fmaf(s, Wh[widx], ah);
    }
    const size_t idx = (size_t)row * Hn + j;
    jcz[idx] = az; jcr[idx] = ar; jch[idx] = ah;
}

__global__ void reduce_kernel(const float* __restrict__ t2, float* __restrict__ out)
{
    const int idx = blockIdx.x * blockDim.x + threadIdx.x;
    const int b = idx >> 8, j = idx & 255;
    const float* p = t2 + (size_t)b * (Nn * Hn) + j;
    float acc = 0.0f;
    for (int n = 0; n < Nn; n++) acc += p[(size_t)n * Hn];
    out[idx] = acc;
}

// ---------------- launch ----------------
extern "C" void kernel_launch(void* const* d_in, const int* in_sizes, int n_in,
                              void* d_out, int out_size)
{
    const float* jets  = (const float*)d_in[0];
    const float* dads  = (const float*)d_in[1];
    const float* W_emb = (const float*)d_in[2];
    const float* b_emb = (const float*)d_in[3];
    const float* W_msg = (const float*)d_in[4];
    const float* b_msg = (const float*)d_in[5];
    const float* Wz    = (const float*)d_in[6];
    const float* Uz    = (const float*)d_in[7];
    const float* bz    = (const float*)d_in[8];
    const float* Wr    = (const float*)d_in[9];
    const float* Ur    = (const float*)d_in[10];
    const float* br    = (const float*)d_in[11];
    const float* Wh    = (const float*)d_in[12];
    const float* Uh    = (const float*)d_in[13];
    const float* bh    = (const float*)d_in[14];
    const float* W_r1  = (const float*)d_in[15];
    const float* b_r1  = (const float*)d_in[16];
    const float* W_r2  = (const float*)d_in[17];
    const float* b_r2  = (const float*)d_in[18];
    float* out = (float*)d_out;

    float *h,*t,*m,*z,*rh,*jcz,*jcr,*jch,*t2;
    cudaGetSymbolAddress((void**)&h,   g_h);
    cudaGetSymbolAddress((void**)&t,   g_t);
    cudaGetSymbolAddress((void**)&m,   g_m);
    cudaGetSymbolAddress((void**)&z,   g_z);
    cudaGetSymbolAddress((void**)&rh,  g_rh);
    cudaGetSymbolAddress((void**)&jcz, g_jcz);
    cudaGetSymbolAddress((void**)&jcr, g_jcr);
    cudaGetSymbolAddress((void**)&jch, g_jch);
    cudaGetSymbolAddress((void**)&t2,  g_t2);

    static bool attr_done = false;
    if (!attr_done) {
        cudaFuncSetAttribute(tc_gemm<EPI_BIAS>,      cudaFuncAttributeMaxDynamicSharedMemorySize, SMEM_BYTES);
        cudaFuncSetAttribute(tc_gemm<EPI_TANH>,      cudaFuncAttributeMaxDynamicSharedMemorySize, SMEM_BYTES);
        cudaFuncSetAttribute(tc_gemm<EPI_TANH_BIAS>, cudaFuncAttributeMaxDynamicSharedMemorySize, SMEM_BYTES);
        cudaFuncSetAttribute(tc_gemm<EPI_SIG>,       cudaFuncAttributeMaxDynamicSharedMemorySize, SMEM_BYTES);
        cudaFuncSetAttribute(tc_gemm<EPI_SIGH>,      cudaFuncAttributeMaxDynamicSharedMemorySize, SMEM_BYTES);
        cudaFuncSetAttribute(tc_gemm<EPI_GRU>,       cudaFuncAttributeMaxDynamicSharedMemorySize, SMEM_BYTES);
        attr_done = true;
    }

    emb_kernel<<<ROWS, Hn>>>(jets, W_emb, b_emb, h);
    jc_kernel<<<ROWS, Hn>>>(jets, Wz, Wr, Wh, bz, br, bh, jcz, jcr, jch);

    dim3 grid(Hn/128, ROWS/128);   // (2, 128)
    for (int it = 0; it < N_ITERS; it++) {
        // t = h @ W_msg + b_msg
        tc_gemm<EPI_BIAS><<<grid, 256, SMEM_BYTES>>>(h, nullptr, W_msg, nullptr,
            b_msg, nullptr, nullptr, nullptr, t, 256, 0);
        // m = tanh(dads @ t)   (batched)
        tc_gemm<EPI_TANH><<<grid, 256, SMEM_BYTES>>>(dads, nullptr, t, nullptr,
            nullptr, nullptr, nullptr, nullptr, m, 256, 1);
        // z = sigmoid(m@Wz[:H] + h@Uz + jc_z)
        tc_gemm<EPI_SIG><<<grid, 256, SMEM_BYTES>>>(m, h, Wz, Uz,
            nullptr, jcz, nullptr, nullptr, z, 512, 0);
        // rh = sigmoid(m@Wr[:H] + h@Ur + jc_r) * h
        tc_gemm<EPI_SIGH><<<grid, 256, SMEM_BYTES>>>(m, h, Wr, Ur,
            nullptr, jcr, h, nullptr, rh, 512, 0);
        // h = (1-z)*h + z*tanh(m@Wh[:H] + rh@Uh + jc_h)
        tc_gemm<EPI_GRU><<<grid, 256, SMEM_BYTES>>>(m, rh, Wh, Uh,
            nullptr, jch, h, z, h, 512, 0);
    }

    tc_gemm<EPI_TANH_BIAS><<<grid, 256, SMEM_BYTES>>>(h, nullptr, W_r1, nullptr,
        b_r1, nullptr, nullptr, nullptr, t, 256, 0);
    tc_gemm<EPI_BIAS><<<grid, 256, SMEM_BYTES>>>(t, nullptr, W_r2, nullptr,
        b_r2, nullptr, nullptr, nullptr, t2, 256, 0);
    reduce_kernel<<<Bn, 256>>>(t2, out);
}

// round 5
// speedup vs baseline: 2.9677x; 1.1848x over previous
#include <cuda_runtime.h>
#include <mma.h>
#include <cuda_bf16.h>
#include <cstdint>
#include <math.h>

using namespace nvcuda;

// ---------------- problem dims ----------------
#define Bn 64
#define Nn 256
#define Fn 16
#define Hn 256
#define ROWS (Bn*Nn)          // 16384
#define N_ITERS 10

// ---------------- scratch ----------------
__device__ float g_h  [ROWS*Hn];
__device__ float g_t  [ROWS*Hn];
__device__ float g_m  [ROWS*Hn];
__device__ float g_z  [ROWS*Hn];
__device__ float g_rh [ROWS*Hn];
__device__ float g_jcz[ROWS*Hn];
__device__ float g_jcr[ROWS*Hn];
__device__ float g_jch[ROWS*Hn];
__device__ float g_t2 [ROWS*Hn];

__device__ __forceinline__ float sigf(float x) { return 1.0f / (1.0f + expf(-x)); }

// ---------------- bf16-split wmma GEMM ----------------
// C[M,N] = epi(A[M,K] @ B[K,N] + extras). Block tile 128x128, 8 warps (2x4),
// warp tile 64x32, K-chunk 32, 2-way bf16 split x 3 passes.
// 2 CTAs/SM (launch_bounds 256,2) -> 16 warps/SM, single wave at grid=256.
enum { EPI_BIAS = 0, EPI_TANH, EPI_TANH_BIAS, EPI_SIG, EPI_SIGH, EPI_GRU };

// SMEM layout (bf16 elements)
#define LDA 40                  // 32 + 8 pad bf16
#define LDB 136                 // 128 + 8 pad bf16
#define A_BYTES (128*LDA*2)     // 10240 per (hi|lo)
#define B_BYTES (32*LDB*2)      // 8704 per (hi|lo)
#define AHI_OFF 0
#define ALO_OFF (A_BYTES)
#define BHI_OFF (2*A_BYTES)
#define BLO_OFF (2*A_BYTES + B_BYTES)
#define BUF_STRIDE (2*A_BYTES + 2*B_BYTES) // 37888
#define SMEM_BYTES (2*BUF_STRIDE)          // 75776 (>= 64KB C staging)

__device__ __forceinline__ void split4(float4 v, uint2& hi, uint2& lo) {
    __nv_bfloat162 h01 = __floats2bfloat162_rn(v.x, v.y);
    __nv_bfloat162 h23 = __floats2bfloat162_rn(v.z, v.w);
    float r0 = v.x - __low2float(h01), r1 = v.y - __high2float(h01);
    float r2 = v.z - __low2float(h23), r3 = v.w - __high2float(h23);
    __nv_bfloat162 l01 = __floats2bfloat162_rn(r0, r1);
    __nv_bfloat162 l23 = __floats2bfloat162_rn(r2, r3);
    hi.x = *(uint32_t*)&h01; hi.y = *(uint32_t*)&h23;
    lo.x = *(uint32_t*)&l01; lo.y = *(uint32_t*)&l23;
}

template<int EPI>
__global__ void __launch_bounds__(256, 2)
tc_gemm(const float* A0, const float* A1,
        const float* B0, const float* B1,
        const float* __restrict__ bias, const float* __restrict__ jc,
        const float* __restrict__ Hb, const float* __restrict__ Zb,
        float* C, int K, int batched)
{
    extern __shared__ char sm[];

    const int tid = threadIdx.x, wid = tid >> 5;
    const int bn = blockIdx.x * 128, bm = blockIdx.y * 128;
    const int warp_m = wid >> 2;        // 0..1 -> 64 rows
    const int warp_n = wid & 3;         // 0..3 -> 32 cols

    const float* Ab = A0; const float* Bb = B0;
    int am = bm;
    if (batched) {
        const int b = bm >> 8;
        Ab = A0 + (size_t)b * (Nn * Hn);
        Bb = B0 + (size_t)b * (Nn * Hn);
        am = bm & (Nn - 1);
    }

    const int NC = K >> 5;

    auto srcs = [&](int kb, const float*& a, const float*& b) {
        const int kk = (kb & 7) * 32;
        if (kb < 8) { a = Ab + (size_t)am * Hn + kk; b = Bb + (size_t)kk * Hn + bn; }
        else        { a = A1 + (size_t)bm * Hn + kk; b = B1 + (size_t)kk * Hn + bn; }
    };

    // load gmem chunk, bf16-split, store to smem buffer (no long-lived staging regs)
    auto commit = [&](int buf, int kb) {
        const float *a, *b; srcs(kb, a, b);
        char* base = sm + buf * BUF_STRIDE;
        #pragma unroll
        for (int i = 0; i < 4; i++) {
            const int f = tid + i * 256;
            float4 va = *(const float4*)(a + (size_t)(f >> 3) * Hn + (f & 7) * 4);
            float4 vb = *(const float4*)(b + (size_t)(f >> 5) * Hn + (f & 31) * 4);
            uint2 hi, lo;
            {
                const int row = f >> 3, c4 = f & 7;
                split4(va, hi, lo);
                const uint32_t off = (uint32_t)(row * LDA + c4 * 4) * 2;
                *(uint2*)(base + AHI_OFF + off) = hi;
                *(uint2*)(base + ALO_OFF + off) = lo;
            }
            {
                const int row = f >> 5, c4 = f & 31;
                split4(vb, hi, lo);
                const uint32_t off = (uint32_t)(row * LDB + c4 * 4) * 2;
                *(uint2*)(base + BHI_OFF + off) = hi;
                *(uint2*)(base + BLO_OFF + off) = lo;
            }
        }
    };

    wmma::fragment<wmma::accumulator, 16, 16, 16, float> acc[4][2];
    #pragma unroll
    for (int mi = 0; mi < 4; mi++)
        #pragma unroll
        for (int ni = 0; ni < 2; ni++)
            wmma::fill_fragment(acc[mi][ni], 0.0f);

    commit(0, 0);
    __syncthreads();

    for (int kb = 0; kb < NC; kb++) {
        // prefetch next chunk into other buffer (overlaps compute via occupancy)
        if (kb + 1 < NC) commit((kb + 1) & 1, kb + 1);

        const char* base = sm + (kb & 1) * BUF_STRIDE;
        const __nv_bfloat16* Ahi = (const __nv_bfloat16*)(base + AHI_OFF);
        const __nv_bfloat16* Alo = (const __nv_bfloat16*)(base + ALO_OFF);
        const __nv_bfloat16* Bhi = (const __nv_bfloat16*)(base + BHI_OFF);
        const __nv_bfloat16* Blo = (const __nv_bfloat16*)(base + BLO_OFF);

        #pragma unroll
        for (int kk = 0; kk < 2; kk++) {
            #pragma unroll
            for (int ni = 0; ni < 2; ni++) {
                wmma::fragment<wmma::matrix_b, 16, 16, 16, __nv_bfloat16, wmma::row_major> bh, bl;
                wmma::load_matrix_sync(bh, Bhi + (kk * 16) * LDB + warp_n * 32 + ni * 16, LDB);
                wmma::load_matrix_sync(bl, Blo + (kk * 16) * LDB + warp_n * 32 + ni * 16, LDB);
                #pragma unroll
                for (int mi = 0; mi < 4; mi++) {
                    wmma::fragment<wmma::matrix_a, 16, 16, 16, __nv_bfloat16, wmma::row_major> ah, al;
                    wmma::load_matrix_sync(ah, Ahi + (warp_m * 64 + mi * 16) * LDA + kk * 16, LDA);
                    wmma::load_matrix_sync(al, Alo + (warp_m * 64 + mi * 16) * LDA + kk * 16, LDA);
                    wmma::mma_sync(acc[mi][ni], ah, bl, acc[mi][ni]);
                    wmma::mma_sync(acc[mi][ni], al, bh, acc[mi][ni]);
                    wmma::mma_sync(acc[mi][ni], ah, bh, acc[mi][ni]);
                }
            }
        }
        __syncthreads();
    }

    // ---------------- epilogue via smem staging ----------------
    float* Cs = (float*)sm;    // 128x128 floats (operand smem dead now)
    #pragma unroll
    for (int mi = 0; mi < 4; mi++)
        #pragma unroll
        for (int ni = 0; ni < 2; ni++)
            wmma::store_matrix_sync(Cs + (warp_m * 64 + mi * 16) * 128 + warp_n * 32 + ni * 16,
                                    acc[mi][ni], 128, wmma::mem_row_major);
    __syncthreads();

    #pragma unroll
    for (int i = 0; i < 16; i++) {
        const int f = tid + i * 256;
        const int row = f >> 5, c4 = f & 31;
        const int grow = bm + row, gcolb = bn + c4 * 4;
        const size_t base = (size_t)grow * Hn + gcolb;
        float4 v = *(float4*)(Cs + row * 128 + c4 * 4);

        if (EPI == EPI_BIAS || EPI == EPI_TANH_BIAS) {
            float4 bv = *(const float4*)(bias + gcolb);
            v.x += bv.x; v.y += bv.y; v.z += bv.z; v.w += bv.w;
            if (EPI == EPI_TANH_BIAS) { v.x=tanhf(v.x); v.y=tanhf(v.y); v.z=tanhf(v.z); v.w=tanhf(v.w); }
        } else if (EPI == EPI_TANH) {
            v.x=tanhf(v.x); v.y=tanhf(v.y); v.z=tanhf(v.z); v.w=tanhf(v.w);
        } else if (EPI == EPI_SIG) {
            float4 jv = *(const float4*)(jc + base);
            v.x=sigf(v.x+jv.x); v.y=sigf(v.y+jv.y); v.z=sigf(v.z+jv.z); v.w=sigf(v.w+jv.w);
        } else if (EPI == EPI_SIGH) {
            float4 jv = *(const float4*)(jc + base);
            float4 hv = *(const float4*)(Hb + base);
            v.x=sigf(v.x+jv.x)*hv.x; v.y=sigf(v.y+jv.y)*hv.y;
            v.z=sigf(v.z+jv.z)*hv.z; v.w=sigf(v.w+jv.w)*hv.w;
        } else if (EPI == EPI_GRU) {
            float4 jv = *(const float4*)(jc + base);
            float4 hv = *(const float4*)(Hb + base);
            float4 zv = *(const float4*)(Zb + base);
            float t0=tanhf(v.x+jv.x), t1=tanhf(v.y+jv.y), t2=tanhf(v.z+jv.z), t3=tanhf(v.w+jv.w);
            v.x = hv.x + zv.x*(t0-hv.x); v.y = hv.y + zv.y*(t1-hv.y);
            v.z = hv.z + zv.z*(t2-hv.z); v.w = hv.w + zv.w*(t3-hv.w);
        }
        *(float4*)(C + base) = v;
    }
}

// ---------------- small kernels ----------------
__global__ void emb_kernel(const float* __restrict__ jets, const float* __restrict__ W_emb,
                           const float* __restrict__ b_emb, float* __restrict__ h)
{
    const int row = blockIdx.x, j = threadIdx.x;
    __shared__ float sj[Fn];
    if (j < Fn) sj[j] = jets[(size_t)row * Fn + j];
    __syncthreads();
    float acc = b_emb[j];
    #pragma unroll
    for (int k = 0; k < Fn; k++) acc = fmaf(sj[k], W_emb[k * Hn + j], acc);
    h[(size_t)row * Hn + j] = tanhf(acc);
}

__global__ void jc_kernel(const float* __restrict__ jets,
                          const float* __restrict__ Wz, const float* __restrict__ Wr,
                          const float* __restrict__ Wh,
                          const float* __restrict__ bz, const float* __restrict__ br,
                          const float* __restrict__ bh,
                          float* jcz, float* jcr, float* jch)
{
    const int row = blockIdx.x, j = threadIdx.x;
    __shared__ float sj[Fn];
    if (j < Fn) sj[j] = jets[(size_t)row * Fn + j];
    __syncthreads();
    float az = bz[j], ar = br[j], ah = bh[j];
    #pragma unroll
    for (int k = 0; k < Fn; k++) {
        const float s = sj[k];
        const int widx = (Hn + k) * Hn + j;
        az = fmaf(s, Wz[widx], az);
        ar = fmaf(s, Wr[widx], ar);
        ah = fmaf(s, Wh[widx], ah);
    }
    const size_t idx = (size_t)row * Hn + j;
    jcz[idx] = az; jcr[idx] = ar; jch[idx] = ah;
}

__global__ void reduce_kernel(const float* __restrict__ t2, float* __restrict__ out)
{
    const int idx = blockIdx.x * blockDim.x + threadIdx.x;
    const int b = idx >> 8, j = idx & 255;
    const float* p = t2 + (size_t)b * (Nn * Hn) + j;
    float acc = 0.0f;
    for (int n = 0; n < Nn; n++) acc += p[(size_t)n * Hn];
    out[idx] = acc;
}

// ---------------- launch ----------------
extern "C" void kernel_launch(void* const* d_in, const int* in_sizes, int n_in,
                              void* d_out, int out_size)
{
    const float* jets  = (const float*)d_in[0];
    const float* dads  = (const float*)d_in[1];
    const float* W_emb = (const float*)d_in[2];
    const float* b_emb = (const float*)d_in[3];
    const float* W_msg = (const float*)d_in[4];
    const float* b_msg = (const float*)d_in[5];
    const float* Wz    = (const float*)d_in[6];
    const float* Uz    = (const float*)d_in[7];
    const float* bz    = (const float*)d_in[8];
    const float* Wr    = (const float*)d_in[9];
    const float* Ur    = (const float*)d_in[10];
    const float* br    = (const float*)d_in[11];
    const float* Wh    = (const float*)d_in[12];
    const float* Uh    = (const float*)d_in[13];
    const float* bh    = (const float*)d_in[14];
    const float* W_r1  = (const float*)d_in[15];
    const float* b_r1  = (const float*)d_in[16];
    const float* W_r2  = (const float*)d_in[17];
    const float* b_r2  = (const float*)d_in[18];
    float* out = (float*)d_out;

    float *h,*t,*m,*z,*rh,*jcz,*jcr,*jch,*t2;
    cudaGetSymbolAddress((void**)&h,   g_h);
    cudaGetSymbolAddress((void**)&t,   g_t);
    cudaGetSymbolAddress((void**)&m,   g_m);
    cudaGetSymbolAddress((void**)&z,   g_z);
    cudaGetSymbolAddress((void**)&rh,  g_rh);
    cudaGetSymbolAddress((void**)&jcz, g_jcz);
    cudaGetSymbolAddress((void**)&jcr, g_jcr);
    cudaGetSymbolAddress((void**)&jch, g_jch);
    cudaGetSymbolAddress((void**)&t2,  g_t2);

    static bool attr_done = false;
    if (!attr_done) {
        cudaFuncSetAttribute(tc_gemm<EPI_BIAS>,      cudaFuncAttributeMaxDynamicSharedMemorySize, SMEM_BYTES);
        cudaFuncSetAttribute(tc_gemm<EPI_TANH>,      cudaFuncAttributeMaxDynamicSharedMemorySize, SMEM_BYTES);
        cudaFuncSetAttribute(tc_gemm<EPI_TANH_BIAS>, cudaFuncAttributeMaxDynamicSharedMemorySize, SMEM_BYTES);
        cudaFuncSetAttribute(tc_gemm<EPI_SIG>,       cudaFuncAttributeMaxDynamicSharedMemorySize, SMEM_BYTES);
        cudaFuncSetAttribute(tc_gemm<EPI_SIGH>,      cudaFuncAttributeMaxDynamicSharedMemorySize, SMEM_BYTES);
        cudaFuncSetAttribute(tc_gemm<EPI_GRU>,       cudaFuncAttributeMaxDynamicSharedMemorySize, SMEM_BYTES);
        attr_done = true;
    }

    emb_kernel<<<ROWS, Hn>>>(jets, W_emb, b_emb, h);
    jc_kernel<<<ROWS, Hn>>>(jets, Wz, Wr, Wh, bz, br, bh, jcz, jcr, jch);

    dim3 grid(Hn/128, ROWS/128);   // (2, 128)
    for (int it = 0; it < N_ITERS; it++) {
        tc_gemm<EPI_BIAS><<<grid, 256, SMEM_BYTES>>>(h, nullptr, W_msg, nullptr,
            b_msg, nullptr, nullptr, nullptr, t, 256, 0);
        tc_gemm<EPI_TANH><<<grid, 256, SMEM_BYTES>>>(dads, nullptr, t, nullptr,
            nullptr, nullptr, nullptr, nullptr, m, 256, 1);
        tc_gemm<EPI_SIG><<<grid, 256, SMEM_BYTES>>>(m, h, Wz, Uz,
            nullptr, jcz, nullptr, nullptr, z, 512, 0);
        tc_gemm<EPI_SIGH><<<grid, 256, SMEM_BYTES>>>(m, h, Wr, Ur,
            nullptr, jcr, h, nullptr, rh, 512, 0);
        tc_gemm<EPI_GRU><<<grid, 256, SMEM_BYTES>>>(m, rh, Wh, Uh,
            nullptr, jch, h, z, h, 512, 0);
    }

    tc_gemm<EPI_TANH_BIAS><<<grid, 256, SMEM_BYTES>>>(h, nullptr, W_r1, nullptr,
        b_r1, nullptr, nullptr, nullptr, t, 256, 0);
    tc_gemm<EPI_BIAS><<<grid, 256, SMEM_BYTES>>>(t, nullptr, W_r2, nullptr,
        b_r2, nullptr, nullptr, nullptr, t2, 256, 0);
    reduce_kernel<<<Bn, 256>>>(t2, out);
}

// round 6
// speedup vs baseline: 3.0543x; 1.0292x over previous
#include <cuda_runtime.h>
#include <mma.h>
#include <cuda_bf16.h>
#include <cstdint>
#include <math.h>

using namespace nvcuda;
typedef __nv_bfloat16 bf16;

// ---------------- problem dims ----------------
#define Bn 64
#define Nn 256
#define Fn 16
#define Hn 256
#define ROWS (Bn*Nn)          // 16384
#define N_ITERS 10
#define PLANE (ROWS*Hn)       // 4194304

// ---------------- scratch ----------------
// fp32 buffers (elementwise consumers)
__device__ float g_h  [PLANE];
__device__ float g_z  [PLANE];
__device__ float g_jcz[PLANE];
__device__ float g_jcr[PLANE];
__device__ float g_jch[PLANE];
__device__ float g_t2 [PLANE];
// bf16 hi/lo planes (GEMM operands)
__device__ bf16 g_hP [2*PLANE];
__device__ bf16 g_tP [2*PLANE];
__device__ bf16 g_mP [2*PLANE];
__device__ bf16 g_rhP[2*PLANE];
__device__ bf16 g_daP[2*PLANE];
// weight planes: msg(65536) zr(262144) hB(131072) r1(65536) r2(65536) = 589824
#define WOFF_MSG 0
#define WOFF_ZR  65536
#define WOFF_HB  327680
#define WOFF_R1  458752
#define WOFF_R2  524288
#define WTOTAL   589824
__device__ bf16 g_wH[WTOTAL];
__device__ bf16 g_wL[WTOTAL];

__device__ __forceinline__ float sigf(float x) { return 1.0f / (1.0f + expf(-x)); }

__device__ __forceinline__ uint32_t smem_u32(const void* p) {
    return (uint32_t)__cvta_generic_to_shared(p);
}
#define CP16(dst, src) asm volatile("cp.async.cg.shared.global [%0], [%1], 16;" :: "r"(dst), "l"(src))
#define CP_COMMIT()    asm volatile("cp.async.commit_group;" ::: "memory")
#define CP_WAIT(n)     asm volatile("cp.async.wait_group %0;" :: "n"(n) : "memory")

// split fp32 -> (hi, lo) bf16
__device__ __forceinline__ void split1(float v, bf16& h, bf16& l) {
    h = __float2bfloat16(v);
    l = __float2bfloat16(v - __bfloat162float(h));
}
// write float4 as hi/lo planes (8B each)
__device__ __forceinline__ void store_planes(bf16* Ph, bf16* Pl, size_t idx, float4 v) {
    __nv_bfloat162 h01 = __floats2bfloat162_rn(v.x, v.y);
    __nv_bfloat162 h23 = __floats2bfloat162_rn(v.z, v.w);
    float r0 = v.x - __low2float(h01), r1 = v.y - __high2float(h01);
    float r2 = v.z - __low2float(h23), r3 = v.w - __high2float(h23);
    __nv_bfloat162 l01 = __floats2bfloat162_rn(r0, r1);
    __nv_bfloat162 l23 = __floats2bfloat162_rn(r2, r3);
    uint2 hv, lv;
    hv.x = *(uint32_t*)&h01; hv.y = *(uint32_t*)&h23;
    lv.x = *(uint32_t*)&l01; lv.y = *(uint32_t*)&l23;
    *(uint2*)(Ph + idx) = hv;
    *(uint2*)(Pl + idx) = lv;
}

// ---------------- GEMM: cp.async 3-stage pipeline, bf16-split planes ----------------
enum { EPI_T = 0, EPI_M, EPI_ZR, EPI_GRU, EPI_R1, EPI_R2 };

#define STAGES 3
#define LDA 40                  // bf16; 80B rows (16B multiple)
#define LDB 136                 // bf16; 272B rows
#define AHI_OFF 0
#define ALO_OFF 10240           // 128*40*2
#define BHI_OFF 20480
#define BLO_OFF 29184           // +32*136*2
#define STAGE_BYTES 37888
#define SMEM_BYTES (STAGES*STAGE_BYTES)   // 113664 (>= 64KB C staging)

template<int EPI>
__global__ void __launch_bounds__(256, 2)
tc_gemm(const bf16* __restrict__ A0h, const bf16* __restrict__ A0l,
        const bf16* __restrict__ A1h, const bf16* __restrict__ A1l,
        const bf16* __restrict__ Bh,  const bf16* __restrict__ Bl,
        int NB, int K, int batched,
        const float* __restrict__ bias,
        const float* __restrict__ jc,  const float* __restrict__ jc2,
        const float* __restrict__ Hb,  const float* __restrict__ Zb,
        float* Cf, bf16* Ch, bf16* Cl)
{
    extern __shared__ char sm[];
    const uint32_t smaddr = smem_u32(sm);

    const int tid = threadIdx.x, wid = tid >> 5;
    const int bn = blockIdx.x * 128, bm = blockIdx.y * 128;
    const int warp_m = wid >> 2;        // 2 x 4 warps, warp tile 64x32
    const int warp_n = wid & 3;

    int am = bm;
    size_t aoff = 0, boff = 0;
    if (batched) {
        const int b = bm >> 8;
        aoff = (size_t)b * (Nn * Hn);
        boff = (size_t)b * (Nn * Hn);
        am = bm & (Nn - 1);
    }

    const int NC = K >> 5;

    auto issue = [&](int kb) {
        const int buf = kb % STAGES;
        const uint32_t sb = smaddr + buf * STAGE_BYTES;
        const int kk = (kb & 7) * 32;
        const bf16 *ah, *al; int arow;
        if (kb < 8) { ah = A0h + aoff; al = A0l + aoff; arow = am; }
        else        { ah = A1h;        al = A1l;        arow = bm; }
        #pragma unroll
        for (int i = 0; i < 2; i++) {
            const int c = tid + i * 256;
            {   // A: 128 rows x 4 chunks of 8 bf16
                const int r = c >> 2, c8 = (c & 3) * 8;
                const bf16* s1 = ah + (size_t)(arow + r) * Hn + kk + c8;
                const bf16* s2 = al + (size_t)(arow + r) * Hn + kk + c8;
                const uint32_t d = sb + AHI_OFF + (uint32_t)(r * LDA + c8) * 2;
                CP16(d, s1);
                CP16(d + (ALO_OFF - AHI_OFF), s2);
            }
            {   // B: 32 rows x 16 chunks of 8 bf16
                const int r = c >> 4, c8 = (c & 15) * 8;
                const bf16* s1 = Bh + boff + (size_t)(kb * 32 + r) * NB + bn + c8;
                const bf16* s2 = Bl + boff + (size_t)(kb * 32 + r) * NB + bn + c8;
                const uint32_t d = sb + BHI_OFF + (uint32_t)(r * LDB + c8) * 2;
                CP16(d, s1);
                CP16(d + (BLO_OFF - BHI_OFF), s2);
            }
        }
    };

    wmma::fragment<wmma::accumulator, 16, 16, 16, float> acc[4][2];
    #pragma unroll
    for (int mi = 0; mi < 4; mi++)
        #pragma unroll
        for (int ni = 0; ni < 2; ni++)
            wmma::fill_fragment(acc[mi][ni], 0.0f);

    // prologue: stages 0..STAGES-2
    issue(0); CP_COMMIT();
    if (NC > 1) issue(1);
    CP_COMMIT();

    for (int kb = 0; kb < NC; kb++) {
        CP_WAIT(1);            // stage kb landed
        __syncthreads();       // also: all warps done with buf (kb-1)%S

        if (kb + STAGES - 1 < NC) issue(kb + STAGES - 1);
        CP_COMMIT();

        const char* base = sm + (kb % STAGES) * STAGE_BYTES;
        const bf16* Ahi = (const bf16*)(base + AHI_OFF);
        const bf16* Alo = (const bf16*)(base + ALO_OFF);
        const bf16* Bhi = (const bf16*)(base + BHI_OFF);
        const bf16* Blo = (const bf16*)(base + BLO_OFF);

        #pragma unroll
        for (int kk = 0; kk < 2; kk++) {
            wmma::fragment<wmma::matrix_b, 16, 16, 16, bf16, wmma::row_major> bh[2], bl[2];
            #pragma unroll
            for (int ni = 0; ni < 2; ni++) {
                wmma::load_matrix_sync(bh[ni], Bhi + (kk * 16) * LDB + warp_n * 32 + ni * 16, LDB);
                wmma::load_matrix_sync(bl[ni], Blo + (kk * 16) * LDB + warp_n * 32 + ni * 16, LDB);
            }
            #pragma unroll
            for (int mi = 0; mi < 4; mi++) {
                wmma::fragment<wmma::matrix_a, 16, 16, 16, bf16, wmma::row_major> ah, al;
                wmma::load_matrix_sync(ah, Ahi + (warp_m * 64 + mi * 16) * LDA + kk * 16, LDA);
                wmma::load_matrix_sync(al, Alo + (warp_m * 64 + mi * 16) * LDA + kk * 16, LDA);
                #pragma unroll
                for (int ni = 0; ni < 2; ni++) {
                    wmma::mma_sync(acc[mi][ni], ah, bl[ni], acc[mi][ni]);
                    wmma::mma_sync(acc[mi][ni], al, bh[ni], acc[mi][ni]);
                    wmma::mma_sync(acc[mi][ni], ah, bh[ni], acc[mi][ni]);
                }
            }
        }
    }
    __syncthreads();

    // ---------------- epilogue via smem staging ----------------
    float* Cs = (float*)sm;
    #pragma unroll
    for (int mi = 0; mi < 4; mi++)
        #pragma unroll
        for (int ni = 0; ni < 2; ni++)
            wmma::store_matrix_sync(Cs + (warp_m * 64 + mi * 16) * 128 + warp_n * 32 + ni * 16,
                                    acc[mi][ni], 128, wmma::mem_row_major);
    __syncthreads();

    #pragma unroll
    for (int i = 0; i < 16; i++) {
        const int f = tid + i * 256;
        const int row = f >> 5, c4 = f & 31;
        const int grow = bm + row;
        const int gcol = bn + c4 * 4;
        float4 v = *(float4*)(Cs + row * 128 + c4 * 4);

        if (EPI == EPI_T || EPI == EPI_R1) {
            // + bias, (tanh for R1), write planes
            const size_t idx = (size_t)grow * Hn + gcol;
            float4 bv = *(const float4*)(bias + gcol);
            v.x += bv.x; v.y += bv.y; v.z += bv.z; v.w += bv.w;
            if (EPI == EPI_R1) { v.x=tanhf(v.x); v.y=tanhf(v.y); v.z=tanhf(v.z); v.w=tanhf(v.w); }
            store_planes(Ch, Cl, idx, v);
        } else if (EPI == EPI_M) {
            const size_t idx = (size_t)grow * Hn + gcol;
            v.x=tanhf(v.x); v.y=tanhf(v.y); v.z=tanhf(v.z); v.w=tanhf(v.w);
            store_planes(Ch, Cl, idx, v);
        } else if (EPI == EPI_ZR) {
            if (gcol < 256) {        // z = sigmoid(v + jcz)
                const size_t idx = (size_t)grow * Hn + gcol;
                float4 jv = *(const float4*)(jc + idx);
                v.x=sigf(v.x+jv.x); v.y=sigf(v.y+jv.y); v.z=sigf(v.z+jv.z); v.w=sigf(v.w+jv.w);
                *(float4*)(Cf + idx) = v;
            } else {                 // rh = sigmoid(v + jcr) * h
                const size_t idx = (size_t)grow * Hn + (gcol - 256);
                float4 jv = *(const float4*)(jc2 + idx);
                float4 hv = *(const float4*)(Hb + idx);
                v.x=sigf(v.x+jv.x)*hv.x; v.y=sigf(v.y+jv.y)*hv.y;
                v.z=sigf(v.z+jv.z)*hv.z; v.w=sigf(v.w+jv.w)*hv.w;
                store_planes(Ch, Cl, idx, v);
            }
        } else if (EPI == EPI_GRU) {
            const size_t idx = (size_t)grow * Hn + gcol;
            float4 jv = *(const float4*)(jc + idx);
            float4 hv = *(const float4*)(Hb + idx);
            float4 zv = *(const float4*)(Zb + idx);
            float t0=tanhf(v.x+jv.x), t1=tanhf(v.y+jv.y), t2=tanhf(v.z+jv.z), t3=tanhf(v.w+jv.w);
            v.x = hv.x + zv.x*(t0-hv.x); v.y = hv.y + zv.y*(t1-hv.y);
            v.z = hv.z + zv.z*(t2-hv.z); v.w = hv.w + zv.w*(t3-hv.w);
            *(float4*)(Cf + idx) = v;
            store_planes(Ch, Cl, idx, v);
        } else if (EPI == EPI_R2) {
            const size_t idx = (size_t)grow * Hn + gcol;
            float4 bv = *(const float4*)(bias + gcol);
            v.x += bv.x; v.y += bv.y; v.z += bv.z; v.w += bv.w;
            *(float4*)(Cf + idx) = v;
        }
    }
}

// ---------------- split / build kernels ----------------
__global__ void split_plain(const float* __restrict__ src, int n4, bf16* __restrict__ hi, bf16* __restrict__ lo)
{
    const int i = blockIdx.x * 256 + threadIdx.x;
    if (i < n4) {
        float4 v = *(const float4*)(src + i * 4);
        store_planes(hi, lo, (size_t)i * 4, v);
    }
}

// zr B: [512][512]; k<256: [Wz|Wr] rows, k>=256: [Uz|Ur]
__global__ void build_zrB(const float* __restrict__ Wz, const float* __restrict__ Wr,
                          const float* __restrict__ Uz, const float* __restrict__ Ur,
                          bf16* __restrict__ hi, bf16* __restrict__ lo)
{
    const int i = blockIdx.x * 256 + threadIdx.x;   // 262144 elements
    const int k = i >> 9, c = i & 511;
    float v;
    if (k < 256) v = (c < 256) ? Wz[k * Hn + c] : Wr[k * Hn + (c - 256)];
    else         v = (c < 256) ? Uz[(k - 256) * Hn + c] : Ur[(k - 256) * Hn + (c - 256)];
    bf16 h, l; split1(v, h, l);
    hi[i] = h; lo[i] = l;
}

// h B: [512][256]; k<256: Wh rows, k>=256: Uh
__global__ void build_hB(const float* __restrict__ Wh, const float* __restrict__ Uh,
                         bf16* __restrict__ hi, bf16* __restrict__ lo)
{
    const int i = blockIdx.x * 256 + threadIdx.x;   // 131072 elements
    const int k = i >> 8, c = i & 255;
    float v = (k < 256) ? Wh[k * Hn + c] : Uh[(k - 256) * Hn + c];
    bf16 h, l; split1(v, h, l);
    hi[i] = h; lo[i] = l;
}

// ---------------- small kernels ----------------
__global__ void emb_kernel(const float* __restrict__ jets, const float* __restrict__ W_emb,
                           const float* __restrict__ b_emb, float* __restrict__ h,
                           bf16* __restrict__ hPh, bf16* __restrict__ hPl)
{
    const int row = blockIdx.x, j = threadIdx.x;
    __shared__ float sj[Fn];
    if (j < Fn) sj[j] = jets[(size_t)row * Fn + j];
    __syncthreads();
    float acc = b_emb[j];
    #pragma unroll
    for (int k = 0; k < Fn; k++) acc = fmaf(sj[k], W_emb[k * Hn + j], acc);
    const float v = tanhf(acc);
    const size_t idx = (size_t)row * Hn + j;
    h[idx] = v;
    bf16 hi, lo; split1(v, hi, lo);
    hPh[idx] = hi; hPl[idx] = lo;
}

__global__ void jc_kernel(const float* __restrict__ jets,
                          const float* __restrict__ Wz, const float* __restrict__ Wr,
                          const float* __restrict__ Wh,
                          const float* __restrict__ bz, const float* __restrict__ br,
                          const float* __restrict__ bh,
                          float* jcz, float* jcr, float* jch)
{
    const int row = blockIdx.x, j = threadIdx.x;
    __shared__ float sj[Fn];
    if (j < Fn) sj[j] = jets[(size_t)row * Fn + j];
    __syncthreads();
    float az = bz[j], ar = br[j], ah = bh[j];
    #pragma unroll
    for (int k = 0; k < Fn; k++) {
        const float s = sj[k];
        const int widx = (Hn + k) * Hn + j;
        az = fmaf(s, Wz[widx], az);
        ar = fmaf(s, Wr[widx], ar);
        ah = fmaf(s, Wh[widx], ah);
    }
    const size_t idx = (size_t)row * Hn + j;
    jcz[idx] = az; jcr[idx] = ar; jch[idx] = ah;
}

__global__ void reduce_kernel(const float* __restrict__ t2, float* __restrict__ out)
{
    const int idx = blockIdx.x * blockDim.x + threadIdx.x;
    const int b = idx >> 8, j = idx & 255;
    const float* p = t2 + (size_t)b * (Nn * Hn) + j;
    float acc = 0.0f;
    for (int n = 0; n < Nn; n++) acc += p[(size_t)n * Hn];
    out[idx] = acc;
}

// ---------------- launch ----------------
extern "C" void kernel_launch(void* const* d_in, const int* in_sizes, int n_in,
                              void* d_out, int out_size)
{
    const float* jets  = (const float*)d_in[0];
    const float* dads  = (const float*)d_in[1];
    const float* W_emb = (const float*)d_in[2];
    const float* b_emb = (const float*)d_in[3];
    const float* W_msg = (const float*)d_in[4];
    const float* b_msg = (const float*)d_in[5];
    const float* Wz    = (const float*)d_in[6];
    const float* Uz    = (const float*)d_in[7];
    const float* bz    = (const float*)d_in[8];
    const float* Wr    = (const float*)d_in[9];
    const float* Ur    = (const float*)d_in[10];
    const float* br    = (const float*)d_in[11];
    const float* Wh    = (const float*)d_in[12];
    const float* Uh    = (const float*)d_in[13];
    const float* bh    = (const float*)d_in[14];
    const float* W_r1  = (const float*)d_in[15];
    const float* b_r1  = (const float*)d_in[16];
    const float* W_r2  = (const float*)d_in[17];
    const float* b_r2  = (const float*)d_in[18];
    float* out = (float*)d_out;

    float *h, *z, *jcz, *jcr, *jch, *t2;
    bf16 *hP, *tP, *mP, *rhP, *daP, *wH, *wL;
    cudaGetSymbolAddress((void**)&h,   g_h);
    cudaGetSymbolAddress((void**)&z,   g_z);
    cudaGetSymbolAddress((void**)&jcz, g_jcz);
    cudaGetSymbolAddress((void**)&jcr, g_jcr);
    cudaGetSymbolAddress((void**)&jch, g_jch);
    cudaGetSymbolAddress((void**)&t2,  g_t2);
    cudaGetSymbolAddress((void**)&hP,  g_hP);
    cudaGetSymbolAddress((void**)&tP,  g_tP);
    cudaGetSymbolAddress((void**)&mP,  g_mP);
    cudaGetSymbolAddress((void**)&rhP, g_rhP);
    cudaGetSymbolAddress((void**)&daP, g_daP);
    cudaGetSymbolAddress((void**)&wH,  g_wH);
    cudaGetSymbolAddress((void**)&wL,  g_wL);

    bf16 *hPh = hP, *hPl = hP + PLANE;
    bf16 *tPh = tP, *tPl = tP + PLANE;
    bf16 *mPh = mP, *mPl = mP + PLANE;
    bf16 *rhPh = rhP, *rhPl = rhP + PLANE;
    bf16 *daPh = daP, *daPl = daP + PLANE;

    static bool attr_done = false;
    if (!attr_done) {
        cudaFuncSetAttribute(tc_gemm<EPI_T>,   cudaFuncAttributeMaxDynamicSharedMemorySize, SMEM_BYTES);
        cudaFuncSetAttribute(tc_gemm<EPI_M>,   cudaFuncAttributeMaxDynamicSharedMemorySize, SMEM_BYTES);
        cudaFuncSetAttribute(tc_gemm<EPI_ZR>,  cudaFuncAttributeMaxDynamicSharedMemorySize, SMEM_BYTES);
        cudaFuncSetAttribute(tc_gemm<EPI_GRU>, cudaFuncAttributeMaxDynamicSharedMemorySize, SMEM_BYTES);
        cudaFuncSetAttribute(tc_gemm<EPI_R1>,  cudaFuncAttributeMaxDynamicSharedMemorySize, SMEM_BYTES);
        cudaFuncSetAttribute(tc_gemm<EPI_R2>,  cudaFuncAttributeMaxDynamicSharedMemorySize, SMEM_BYTES);
        attr_done = true;
    }

    // one-time (per launch) operand preparation
    split_plain<<<PLANE/4/256, 256>>>(dads, PLANE/4, daPh, daPl);
    split_plain<<<65536/4/256, 256>>>(W_msg, 65536/4, wH + WOFF_MSG, wL + WOFF_MSG);
    split_plain<<<65536/4/256, 256>>>(W_r1,  65536/4, wH + WOFF_R1,  wL + WOFF_R1);
    split_plain<<<65536/4/256, 256>>>(W_r2,  65536/4, wH + WOFF_R2,  wL + WOFF_R2);
    build_zrB<<<262144/256, 256>>>(Wz, Wr, Uz, Ur, wH + WOFF_ZR, wL + WOFF_ZR);
    build_hB<<<131072/256, 256>>>(Wh, Uh, wH + WOFF_HB, wL + WOFF_HB);

    emb_kernel<<<ROWS, Hn>>>(jets, W_emb, b_emb, h, hPh, hPl);
    jc_kernel<<<ROWS, Hn>>>(jets, Wz, Wr, Wh, bz, br, bh, jcz, jcr, jch);

    dim3 grid2(2, ROWS/128);
    dim3 grid4(4, ROWS/128);
    for (int it = 0; it < N_ITERS; it++) {
        // t = h @ W_msg + b_msg  -> t planes
        tc_gemm<EPI_T><<<grid2, 256, SMEM_BYTES>>>(
            hPh, hPl, nullptr, nullptr, wH + WOFF_MSG, wL + WOFF_MSG,
            256, 256, 0, b_msg, nullptr, nullptr, nullptr, nullptr,
            nullptr, tPh, tPl);
        // m = tanh(dads @ t)  (batched) -> m planes
        tc_gemm<EPI_M><<<grid2, 256, SMEM_BYTES>>>(
            daPh, daPl, nullptr, nullptr, tPh, tPl,
            256, 256, 1, nullptr, nullptr, nullptr, nullptr, nullptr,
            nullptr, mPh, mPl);
        // [z|r]: [m|h] @ zrB; z -> fp32, rh = r*h -> planes
        tc_gemm<EPI_ZR><<<grid4, 256, SMEM_BYTES>>>(
            mPh, mPl, hPh, hPl, wH + WOFF_ZR, wL + WOFF_ZR,
            512, 512, 0, nullptr, jcz, jcr, h, nullptr,
            z, rhPh, rhPl);
        // h = (1-z)*h + z*tanh([m|rh] @ hB + jch) -> fp32 + planes
        tc_gemm<EPI_GRU><<<grid2, 256, SMEM_BYTES>>>(
            mPh, mPl, rhPh, rhPl, wH + WOFF_HB, wL + WOFF_HB,
            256, 512, 0, nullptr, jch, nullptr, h, z,
            h, hPh, hPl);
    }

    // readout
    tc_gemm<EPI_R1><<<grid2, 256, SMEM_BYTES>>>(
        hPh, hPl, nullptr, nullptr, wH + WOFF_R1, wL + WOFF_R1,
        256, 256, 0, b_r1, nullptr, nullptr, nullptr, nullptr,
        nullptr, tPh, tPl);
    tc_gemm<EPI_R2><<<grid2, 256, SMEM_BYTES>>>(
        tPh, tPl, nullptr, nullptr, wH + WOFF_R2, wL + WOFF_R2,
        256, 256, 0, b_r2, nullptr, nullptr, nullptr, nullptr,
        t2, nullptr, nullptr);
    reduce_kernel<<<Bn, 256>>>(t2, out);
}